// round 13
// baseline (speedup 1.0000x reference)
#include <cuda_runtime.h>

// ---------------------------------------------------------------------------
// GATSummarizer: 4-layer GAT + mean pool + sigmoid head.
// R7: float4 gather in aggregation (4x fewer load issues), 8-edge-batched
// fill (MLP 8), self-loop emitted by scan, head fused into last agg via
// last-block-done. Core: tf32 3-term-split mma GEMM + fused attn epilogue,
// CSR warp-per-node segment softmax, layer-1 GEMM overlapped with count.
// ---------------------------------------------------------------------------

#define NMAX 50016
#define ETMAX 860032
#define NGRAPH 64

__device__ __align__(16) float g_h0[NMAX * 96];   // GEMM output (current h)
__device__ __align__(16) float g_h1[NMAX * 96];   // aggregated output
__device__ float g_es[NMAX * 2];
__device__ float g_ed[NMAX * 2];
__device__ float g_ebuf[ETMAX * 2];    // slow-path per-edge values
__device__ int   g_cnt[NMAX];
__device__ int   g_begin[NMAX];        // CSR segment start per node
__device__ int   g_cursor[NMAX];
__device__ int   g_csrc[ETMAX];
__device__ int   g_total;
__device__ int   g_done;
__device__ float g_psum[NGRAPH * 96];
__device__ float g_pcnt[NGRAPH];
__device__ int   g_is64_e;
__device__ int   g_is64_b;
// pre-packed W fragments: [layer][ks<=16][nt=12][lane=32][2 regs], tf32 bits
__device__ unsigned g_wp_hi[4 * 16 * 12 * 32 * 2];
__device__ unsigned g_wp_lo[4 * 16 * 12 * 32 * 2];

// ---------------- tf32 split helpers ----------------
__device__ __forceinline__ void split_tf32(float v, unsigned& hi, unsigned& lo) {
    unsigned h;
    asm("cvt.rna.tf32.f32 %0, %1;" : "=r"(h) : "f"(v));
    float r = v - __uint_as_float(h);
    asm("cvt.rna.tf32.f32 %0, %1;" : "=r"(lo) : "f"(r));
    hi = h;
}

__device__ __forceinline__ void mma_tf32(float* d,
                                         unsigned a0, unsigned a1,
                                         unsigned a2, unsigned a3,
                                         unsigned b0, unsigned b1) {
    asm volatile(
        "mma.sync.aligned.m16n8k8.row.col.f32.tf32.tf32.f32 "
        "{%0,%1,%2,%3},{%4,%5,%6,%7},{%8,%9},{%0,%1,%2,%3};"
        : "+f"(d[0]), "+f"(d[1]), "+f"(d[2]), "+f"(d[3])
        : "r"(a0), "r"(a1), "r"(a2), "r"(a3), "r"(b0), "r"(b1));
}

__device__ __forceinline__ int load_idx(const void* p, long long i, int is64) {
    return is64 ? (int)((const long long*)p)[i] : ((const int*)p)[i];
}

// ------------- init (cnt=1 self-loop precount, pools, probe) + wprep -------
__global__ void __launch_bounds__(768) initwprep_k(
    const void* __restrict__ eidx, const void* __restrict__ batch,
    const float* __restrict__ W1, const float* __restrict__ W2,
    const float* __restrict__ W3, const float* __restrict__ W4,
    int N, int nbi) {
    int bid = blockIdx.x;
    int tid = threadIdx.x;
    if (bid < nbi) {
        int i = bid * 768 + tid;
        if (i < N) g_cnt[i] = 1;          // self-loop pre-counted
        if (i < NGRAPH * 96) g_psum[i] = 0.f;
        if (i < NGRAPH) g_pcnt[i] = 0.f;
        if (bid == 0 && tid == 0) {
            g_total = 0;
            g_done = 0;
            const int* e32 = (const int*)eidx;
            int all0 = 1;
            for (int j = 1; j < 64; j += 2) if (e32[j] != 0) all0 = 0;
            g_is64_e = all0;
            const int* b32 = (const int*)batch;
            int base = (N / 2) & ~1;
            all0 = 1;
            for (int j = 1; j < 64; j += 2) if (b32[base + j] != 0) all0 = 0;
            g_is64_b = all0;
        }
        return;
    }
    // ---- wprep: 52 blocks, ks-major across layers {16,12,12,12} ----
    int b = bid - nbi;
    int layer, ks;
    const float* W;
    if (b < 16)      { layer = 0; ks = b;      W = W1; }
    else if (b < 28) { layer = 1; ks = b - 16; W = W2; }
    else if (b < 40) { layer = 2; ks = b - 28; W = W3; }
    else             { layer = 3; ks = b - 40; W = W4; }
    int nt = tid / 64;
    int rem = tid % 64;
    int lane = rem >> 1;
    int reg = rem & 1;
    int tg = lane & 3, g = lane >> 2;
    int krow = ks * 8 + tg + reg * 4;
    int col = nt * 8 + g;
    float v = W[(size_t)krow * 96 + col];
    unsigned hi, lo;
    split_tf32(v, hi, lo);
    int idx = layer * 12288 + (ks * 12 + nt) * 64 + lane * 2 + reg;
    g_wp_hi[idx] = hi;
    g_wp_lo[idx] = lo;
}

// --------------- tensor-core GEMM + fused attention body -------------------
template <int K, int H>
__device__ __forceinline__ void gemm_body(
    const float* __restrict__ A, int layer,
    const float* __restrict__ as, const float* __restrict__ ad,
    int N, int bid) {
    int lane = threadIdx.x & 31, warp = threadIdx.x >> 5;
    int g = lane >> 2, tg = lane & 3;
    int r0 = bid * 128 + warp * 16 + g;          // rows for c0/c1
    int r1 = r0 + 8;                             // rows for c2/c3
    bool ok0 = r0 < N, ok1 = r1 < N;
    const int KS = K / 8;

    float acc[12][4];
    #pragma unroll
    for (int nt = 0; nt < 12; nt++)
        #pragma unroll
        for (int j = 0; j < 4; j++) acc[nt][j] = 0.f;

    const float* Ar0 = A + (size_t)r0 * K;
    const float* Ar1 = A + (size_t)r1 * K;
    const unsigned* wph = g_wp_hi + layer * 12288;
    const unsigned* wpl = g_wp_lo + layer * 12288;

    for (int ks = 0; ks < KS; ks++) {
        int k0 = ks * 8 + tg;
        float v0 = ok0 ? Ar0[k0]     : 0.f;
        float v1 = ok1 ? Ar1[k0]     : 0.f;
        float v2 = ok0 ? Ar0[k0 + 4] : 0.f;
        float v3 = ok1 ? Ar1[k0 + 4] : 0.f;
        unsigned ah0, al0, ah1, al1, ah2, al2, ah3, al3;
        split_tf32(v0, ah0, al0);
        split_tf32(v1, ah1, al1);
        split_tf32(v2, ah2, al2);
        split_tf32(v3, ah3, al3);
        const unsigned* bh = wph + ks * 768 + lane * 2;
        const unsigned* bl = wpl + ks * 768 + lane * 2;
        #pragma unroll
        for (int nt = 0; nt < 12; nt++) {
            uint2 bhv = *(const uint2*)(bh + nt * 64);
            uint2 blv = *(const uint2*)(bl + nt * 64);
            mma_tf32(acc[nt], ah0, ah1, ah2, ah3, bhv.x, bhv.y);  // Ahi*Whi
            mma_tf32(acc[nt], ah0, ah1, ah2, ah3, blv.x, blv.y);  // Ahi*Wlo
            mma_tf32(acc[nt], al0, al1, al2, al3, bhv.x, bhv.y);  // Alo*Whi
        }
    }

    // epilogue: store h0 + fused es/ed
    float es0a = 0.f, es1a = 0.f, ed0a = 0.f, ed1a = 0.f;  // row r0 (heads 0/1)
    float es0b = 0.f, es1b = 0.f, ed0b = 0.f, ed1b = 0.f;  // row r1
    #pragma unroll
    for (int nt = 0; nt < 12; nt++) {
        int c = nt * 8 + tg * 2;
        float av0 = as[c], av1 = as[c + 1];
        float dv0 = ad[c], dv1 = ad[c + 1];
        float ea = av0 * acc[nt][0] + av1 * acc[nt][1];
        float da = dv0 * acc[nt][0] + dv1 * acc[nt][1];
        float eb = av0 * acc[nt][2] + av1 * acc[nt][3];
        float db = dv0 * acc[nt][2] + dv1 * acc[nt][3];
        if (H == 2 && nt >= 6) { es1a += ea; ed1a += da; es1b += eb; ed1b += db; }
        else                   { es0a += ea; ed0a += da; es0b += eb; ed0b += db; }
        if (ok0) *(float2*)(g_h0 + (size_t)r0 * 96 + c) = make_float2(acc[nt][0], acc[nt][1]);
        if (ok1) *(float2*)(g_h0 + (size_t)r1 * 96 + c) = make_float2(acc[nt][2], acc[nt][3]);
    }
    #pragma unroll
    for (int o = 1; o < 4; o <<= 1) {
        es0a += __shfl_xor_sync(0xffffffffu, es0a, o);
        ed0a += __shfl_xor_sync(0xffffffffu, ed0a, o);
        es0b += __shfl_xor_sync(0xffffffffu, es0b, o);
        ed0b += __shfl_xor_sync(0xffffffffu, ed0b, o);
        if (H == 2) {
            es1a += __shfl_xor_sync(0xffffffffu, es1a, o);
            ed1a += __shfl_xor_sync(0xffffffffu, ed1a, o);
            es1b += __shfl_xor_sync(0xffffffffu, es1b, o);
            ed1b += __shfl_xor_sync(0xffffffffu, ed1b, o);
        }
    }
    if (tg == 0) {
        if (H == 2) {
            if (ok0) { g_es[r0 * 2] = es0a; g_es[r0 * 2 + 1] = es1a;
                       g_ed[r0 * 2] = ed0a; g_ed[r0 * 2 + 1] = ed1a; }
            if (ok1) { g_es[r1 * 2] = es0b; g_es[r1 * 2 + 1] = es1b;
                       g_ed[r1 * 2] = ed0b; g_ed[r1 * 2 + 1] = ed1b; }
        } else {
            if (ok0) { g_es[r0] = es0a; g_ed[r0] = ed0a; }
            if (ok1) { g_es[r1] = es0b; g_ed[r1] = ed0b; }
        }
    }
}

// --------------- fused launch: layer-1 GEMM (blocks [0,gb)) + count --------
__global__ void __launch_bounds__(256) gemm1_count_k(
    const float* __restrict__ x, const float* __restrict__ as1,
    const float* __restrict__ ad1, const void* __restrict__ eidx,
    int E, int N, int gb) {
    int bid = blockIdx.x;
    if (bid < gb) {
        gemm_body<128, 2>(x, 0, as1, ad1, N, bid);
        return;
    }
    // count blocks: 8 edges per thread, MLP-batched
    int t = (bid - gb) * 256 + threadIdx.x;
    int base = t * 8;
    if (base >= E) return;
    int is64 = g_is64_e;
    if (!is64 && (E & 7) == 0) {
        const int* dp = (const int*)eidx + E + base;
        int4 a = *(const int4*)dp;
        int4 b = *(const int4*)(dp + 4);
        atomicAdd(&g_cnt[a.x], 1); atomicAdd(&g_cnt[a.y], 1);
        atomicAdd(&g_cnt[a.z], 1); atomicAdd(&g_cnt[a.w], 1);
        atomicAdd(&g_cnt[b.x], 1); atomicAdd(&g_cnt[b.y], 1);
        atomicAdd(&g_cnt[b.z], 1); atomicAdd(&g_cnt[b.w], 1);
    } else {
        int lim = min(base + 8, E);
        for (int i = base; i < lim; i++)
            atomicAdd(&g_cnt[load_idx(eidx, (long long)E + i, is64)], 1);
    }
}

// single-pass scan + self-loop emission (slot beg[v], cursor starts beg+1)
__global__ void scan_k(int N) {
    __shared__ int ws[8];
    __shared__ int sh_off;
    int tid = threadIdx.x;
    int i = blockIdx.x * 256 + tid;
    int lane = tid & 31, warp = tid >> 5;
    int v = (i < N) ? g_cnt[i] : 0;
    int x = v;
    #pragma unroll
    for (int o = 1; o < 32; o <<= 1) {
        int y = __shfl_up_sync(0xffffffffu, x, o);
        if (lane >= o) x += y;
    }
    if (lane == 31) ws[warp] = x;
    __syncthreads();
    if (tid == 0) {
        int run = 0;
        #pragma unroll
        for (int w = 0; w < 8; w++) { int t = ws[w]; ws[w] = run; run += t; }
    }
    __syncthreads();
    int incl = x + ws[warp];
    if (tid == 255) sh_off = atomicAdd(&g_total, incl);
    __syncthreads();
    if (i < N) {
        int beg = sh_off + incl - v;
        g_begin[i] = beg;
        g_csrc[beg] = i;          // self-loop in slot 0
        g_cursor[i] = beg + 1;
    }
}

// fill: 8 edges per thread, MLP-batched
__global__ void fillv_k(const void* __restrict__ eidx, int E) {
    int t = blockIdx.x * 256 + threadIdx.x;
    int base = t * 8;
    if (base >= E) return;
    int is64 = g_is64_e;
    if (!is64 && (E & 7) == 0) {
        const int* sp = (const int*)eidx + base;
        const int* dp = (const int*)eidx + E + base;
        int4 sa = *(const int4*)sp;
        int4 sb = *(const int4*)(sp + 4);
        int4 da = *(const int4*)dp;
        int4 db = *(const int4*)(dp + 4);
        int p0 = atomicAdd(&g_cursor[da.x], 1);
        int p1 = atomicAdd(&g_cursor[da.y], 1);
        int p2 = atomicAdd(&g_cursor[da.z], 1);
        int p3 = atomicAdd(&g_cursor[da.w], 1);
        int p4 = atomicAdd(&g_cursor[db.x], 1);
        int p5 = atomicAdd(&g_cursor[db.y], 1);
        int p6 = atomicAdd(&g_cursor[db.z], 1);
        int p7 = atomicAdd(&g_cursor[db.w], 1);
        g_csrc[p0] = sa.x; g_csrc[p1] = sa.y;
        g_csrc[p2] = sa.z; g_csrc[p3] = sa.w;
        g_csrc[p4] = sb.x; g_csrc[p5] = sb.y;
        g_csrc[p6] = sb.z; g_csrc[p7] = sb.w;
    } else {
        int lim = min(base + 8, E);
        for (int i = base; i < lim; i++) {
            int src = load_idx(eidx, i, is64);
            int dst = load_idx(eidx, (long long)E + i, is64);
            int pos = atomicAdd(&g_cursor[dst], 1);
            g_csrc[pos] = src;
        }
    }
}

// --------------- standalone GEMM (layers 2-4) ------------------------------
template <int K, int H>
__global__ void __launch_bounds__(256) mma_gemm_attn_k(
    int layer, const float* __restrict__ as, const float* __restrict__ ad,
    int N) {
    gemm_body<K, H>(g_h1, layer, as, ad, N, blockIdx.x);
}

// ------------- segment softmax + float4 aggregation (warp/node) ------------
template <int H, bool LAST>
__global__ void agg_k(const float* __restrict__ bias,
                      const void* __restrict__ batch,
                      const float* __restrict__ Wc,
                      const float* __restrict__ bc,
                      float* __restrict__ out, int N) {
    int v = (blockIdx.x * blockDim.x + threadIdx.x) >> 5;
    int lane = threadIdx.x & 31;
    if (v < N) {
        int beg = g_begin[v];
        int deg = g_cnt[v];
        int end = beg + deg;

        float ed0 = g_ed[v * H];
        float ed1 = (H == 2) ? g_ed[v * 2 + 1] : 0.f;

        float inv0, inv1;
        bool act = lane < 24;
        float4 acc4 = make_float4(0.f, 0.f, 0.f, 0.f);
        const float4* h4 = (const float4*)g_h0;

        if (deg <= 32) {
            // ---------- fast path: one edge per lane, registers only ----------
            int s = (lane < deg) ? g_csrc[beg + lane] : 0;
            float e0 = -3.4e38f, e1 = -3.4e38f;
            if (lane < deg) {
                e0 = g_es[s * H] + ed0;
                e0 = (e0 > 0.f) ? e0 : 0.2f * e0;
                if (H == 2) {
                    e1 = g_es[s * 2 + 1] + ed1;
                    e1 = (e1 > 0.f) ? e1 : 0.2f * e1;
                }
            }
            float m0 = e0, m1 = e1;
            #pragma unroll
            for (int o = 16; o; o >>= 1) {
                m0 = fmaxf(m0, __shfl_xor_sync(0xffffffffu, m0, o));
                if (H == 2) m1 = fmaxf(m1, __shfl_xor_sync(0xffffffffu, m1, o));
            }
            float p0 = (lane < deg) ? __expf(e0 - m0) : 0.f;
            float p1 = (H == 2 && lane < deg) ? __expf(e1 - m1) : 0.f;
            float s0 = p0, s1 = p1;
            #pragma unroll
            for (int o = 16; o; o >>= 1) {
                s0 += __shfl_xor_sync(0xffffffffu, s0, o);
                if (H == 2) s1 += __shfl_xor_sync(0xffffffffu, s1, o);
            }
            inv0 = 1.0f / s0;
            inv1 = (H == 2) ? 1.0f / s1 : inv0;

            for (int i = 0; i < deg; i++) {
                int si = __shfl_sync(0xffffffffu, s, i);
                float pi0 = __shfl_sync(0xffffffffu, p0, i);
                float w;
                if (H == 2) {
                    float pi1 = __shfl_sync(0xffffffffu, p1, i);
                    w = (lane < 12) ? pi0 : pi1;
                } else w = pi0;
                if (act) {
                    float4 hv = h4[(size_t)si * 24 + lane];
                    acc4.x += w * hv.x; acc4.y += w * hv.y;
                    acc4.z += w * hv.z; acc4.w += w * hv.w;
                }
            }
        } else {
            // ---------- slow path (rare): spill e/p to g_ebuf ----------
            float m0 = -3.4e38f, m1 = -3.4e38f;
            for (int i = beg + lane; i < end; i += 32) {
                int s = g_csrc[i];
                float e0 = g_es[s * H] + ed0;
                e0 = (e0 > 0.f) ? e0 : 0.2f * e0;
                g_ebuf[i * H] = e0;
                m0 = fmaxf(m0, e0);
                if (H == 2) {
                    float e1 = g_es[s * 2 + 1] + ed1;
                    e1 = (e1 > 0.f) ? e1 : 0.2f * e1;
                    g_ebuf[i * 2 + 1] = e1;
                    m1 = fmaxf(m1, e1);
                }
            }
            #pragma unroll
            for (int o = 16; o; o >>= 1) {
                m0 = fmaxf(m0, __shfl_xor_sync(0xffffffffu, m0, o));
                if (H == 2) m1 = fmaxf(m1, __shfl_xor_sync(0xffffffffu, m1, o));
            }
            float s0 = 0.f, s1 = 0.f;
            for (int i = beg + lane; i < end; i += 32) {
                float p0 = __expf(g_ebuf[i * H] - m0);
                g_ebuf[i * H] = p0;
                s0 += p0;
                if (H == 2) {
                    float p1 = __expf(g_ebuf[i * 2 + 1] - m1);
                    g_ebuf[i * 2 + 1] = p1;
                    s1 += p1;
                }
            }
            #pragma unroll
            for (int o = 16; o; o >>= 1) {
                s0 += __shfl_xor_sync(0xffffffffu, s0, o);
                if (H == 2) s1 += __shfl_xor_sync(0xffffffffu, s1, o);
            }
            inv0 = 1.0f / s0;
            inv1 = (H == 2) ? 1.0f / s1 : inv0;

            for (int i = beg; i < end; i++) {
                int si = g_csrc[i];
                float w;
                if (H == 2) {
                    float p0 = g_ebuf[i * 2 + 0];
                    float p1 = g_ebuf[i * 2 + 1];
                    w = (lane < 12) ? p0 : p1;
                } else w = g_ebuf[i];
                if (act) {
                    float4 hv = h4[(size_t)si * 24 + lane];
                    acc4.x += w * hv.x; acc4.y += w * hv.y;
                    acc4.z += w * hv.z; acc4.w += w * hv.w;
                }
            }
        }

        if (act) {
            float invv = (H == 2) ? ((lane < 12) ? inv0 : inv1) : inv0;
            const float4 b4v = ((const float4*)bias)[lane];
            float4 o4;
            o4.x = fmaxf(acc4.x * invv + b4v.x, 0.f);
            o4.y = fmaxf(acc4.y * invv + b4v.y, 0.f);
            o4.z = fmaxf(acc4.z * invv + b4v.z, 0.f);
            o4.w = fmaxf(acc4.w * invv + b4v.w, 0.f);
            if (LAST) {
                int gb = load_idx(batch, v, g_is64_b);
                float* ps = g_psum + gb * 96 + lane * 4;
                atomicAdd(ps + 0, o4.x);
                atomicAdd(ps + 1, o4.y);
                atomicAdd(ps + 2, o4.z);
                atomicAdd(ps + 3, o4.w);
                if (lane == 0) atomicAdd(&g_pcnt[gb], 1.0f);
            } else {
                ((float4*)g_h1)[(size_t)v * 24 + lane] = o4;
            }
        }
    }

    if (LAST) {
        // last-block-done: final block computes the sigmoid head
        __shared__ int sh_last;
        __syncthreads();
        if (threadIdx.x == 0) {
            __threadfence();
            int prev = atomicAdd(&g_done, 1);
            sh_last = (prev == (int)gridDim.x - 1) ? 1 : 0;
        }
        __syncthreads();
        if (sh_last) {
            int wid = threadIdx.x >> 5;
            int ln = threadIdx.x & 31;
            for (int g = wid; g < NGRAPH; g += 8) {
                float cnt = fmaxf(g_pcnt[g], 1.0f);
                float acc = 0.f;
                #pragma unroll
                for (int j = 0; j < 3; j++) {
                    int c = ln + 32 * j;
                    acc += (g_psum[g * 96 + c] / cnt) * Wc[c];
                }
                #pragma unroll
                for (int o = 16; o; o >>= 1)
                    acc += __shfl_xor_sync(0xffffffffu, acc, o);
                if (ln == 0)
                    out[g] = 1.0f / (1.0f + __expf(-(acc + bc[0])));
            }
        }
    }
}

// ------------------------------- launch -----------------------------------
extern "C" void kernel_launch(void* const* d_in, const int* in_sizes, int n_in,
                              void* d_out, int out_size) {
    const float* x     = (const float*)d_in[0];
    const void*  eidx  = d_in[1];            // int32 or int64 (auto-detected)
    // d_in[2] edge_weight: ignored by GATConv (edge_dim=None)
    const void*  batch = d_in[3];
    const float* W1  = (const float*)d_in[4];
    const float* as1 = (const float*)d_in[5];
    const float* ad1 = (const float*)d_in[6];
    const float* b1  = (const float*)d_in[7];
    const float* W2  = (const float*)d_in[8];
    const float* as2 = (const float*)d_in[9];
    const float* ad2 = (const float*)d_in[10];
    const float* b2  = (const float*)d_in[11];
    const float* W3  = (const float*)d_in[12];
    const float* as3 = (const float*)d_in[13];
    const float* ad3 = (const float*)d_in[14];
    const float* b3  = (const float*)d_in[15];
    const float* W4  = (const float*)d_in[16];
    const float* as4 = (const float*)d_in[17];
    const float* ad4 = (const float*)d_in[18];
    const float* b4  = (const float*)d_in[19];
    const float* Wc  = (const float*)d_in[20];
    const float* bc  = (const float*)d_in[21];
    float* out = (float*)d_out;

    int N  = in_sizes[3];          // 50000
    int E  = in_sizes[2];          // 800000

    int nbi = (N + 767) / 768;                 // init blocks
    int gb  = (N + 127) / 128;                 // gemm blocks
    int cbE = (E + 2047) / 2048;               // count/fill blocks (8/thread)
    int nbN = (N + 255) / 256;                 // scan blocks
    int wgrid = (int)(((long long)N * 32 + 255) / 256);

    initwprep_k<<<nbi + 52, 768>>>(eidx, batch, W1, W2, W3, W4, N, nbi);
    gemm1_count_k<<<gb + cbE, 256>>>(x, as1, ad1, eidx, E, N, gb);
    scan_k<<<nbN, 256>>>(N);
    fillv_k<<<cbE, 256>>>(eidx, E);

    agg_k<2, false><<<wgrid, 256>>>(b1, batch, Wc, bc, out, N);
    mma_gemm_attn_k<96, 1><<<gb, 256>>>(1, as2, ad2, N);
    agg_k<1, false><<<wgrid, 256>>>(b2, batch, Wc, bc, out, N);
    mma_gemm_attn_k<96, 1><<<gb, 256>>>(2, as3, ad3, N);
    agg_k<1, false><<<wgrid, 256>>>(b3, batch, Wc, bc, out, N);
    mma_gemm_attn_k<96, 1><<<gb, 256>>>(3, as4, ad4, N);
    agg_k<1, true><<<wgrid, 256>>>(b4, batch, Wc, bc, out, N);
}